// round 11
// baseline (speedup 1.0000x reference)
#include <cuda_runtime.h>
#include <math.h>

#define BB 8
#define CC 128
#define HH 160
#define WW 160
#define HW (HH*WW)
#define Hh 80
#define Wh 80

typedef unsigned long long ull;

// ---------------- scratch ----------------------------------------------------
__device__ float g_upflow[BB*2*HW];
__device__ float g_xin[BB*50*HW];
__device__ float g_x1[BB*128*HW];
__device__ float g_x2[BB*64*HW];
__device__ float g_x3[BB*32*HW];

__device__ __forceinline__ float lrelu(float v) { return v > 0.f ? v : 0.1f * v; }

__device__ __forceinline__ void fma2(ull &d, ull a, ull b) {
    asm("fma.rn.f32x2 %0, %1, %2, %0;" : "+l"(d) : "l"(a), "l"(b));
}
__device__ __forceinline__ ull pk(float lo, float hi) {
    ull r;
    asm("mov.b64 %0, {%1, %2};" : "=l"(r) : "f"(lo), "f"(hi));
    return r;
}
__device__ __forceinline__ void upk(float &lo, float &hi, ull p) {
    asm("mov.b64 {%0, %1}, %2;" : "=f"(lo), "=f"(hi) : "l"(p));
}

__device__ __forceinline__ unsigned su(const void* p) {
    return (unsigned)__cvta_generic_to_shared(p);
}
__device__ __forceinline__ void cpa4(unsigned dst, const float* src, bool v) {
    int sz = v ? 4 : 0;
    asm volatile("cp.async.ca.shared.global [%0], [%1], 4, %2;" :: "r"(dst), "l"(src), "r"(sz));
}
#define CPCOMMIT asm volatile("cp.async.commit_group;")
#define CPWAIT(N) asm volatile("cp.async.wait_group %0;" :: "n"(N))

// ---------------- kernel 1: transposed-conv upsampling -----------------------
__global__ void deconv_kernel(const float* __restrict__ flow,
                              const float* __restrict__ conf,
                              const float* __restrict__ wf,
                              const float* __restrict__ wc)
{
    int i = blockIdx.x * blockDim.x + threadIdx.x;
    if (i >= BB * 3 * HW) return;
    int x  = i % WW;
    int y  = (i / WW) % HH;
    int ch = (i / HW) % 3;
    int b  = i / (3 * HW);

    const float* w;
    const float* in;
    if (ch < 2) { w = wf + ch * 16; in = flow + (b * 2 + ch) * (Hh * Wh); }
    else        { w = wc;           in = conf + b * (Hh * Wh); }

    float acc = 0.f;
    #pragma unroll
    for (int ky = 0; ky < 4; ky++) {
        int t = y + 1 - ky;
        if (t & 1) continue;
        int iy = t >> 1;
        if ((unsigned)iy >= Hh) continue;
        #pragma unroll
        for (int kx = 0; kx < 4; kx++) {
            int u = x + 1 - kx;
            if (u & 1) continue;
            int ix = u >> 1;
            if ((unsigned)ix >= Wh) continue;
            acc += in[iy * Wh + ix] * w[ky * 4 + kx];
        }
    }
    if (ch < 2) g_upflow[(b * 2 + ch) * HW + y * WW + x] = acc;
    else        g_xin[((size_t)b * 50 + 49) * HW + y * WW + x] = acc;
}

// ---------------- kernel 2: 7x7 dilated self-correlation ---------------------
__global__ __launch_bounds__(512) void corr_kernel(const float* __restrict__ feats)
{
    __shared__ float2 sm2[2][2][28][32];
    constexpr int TEL = 4 * 28 * 28;            // 3136
    constexpr int NJ  = (TEL + 511) / 512;      // 7
    constexpr int BUF = 2 * 28 * 32 * 2;        // floats per buffer

    int b   = blockIdx.z;
    int ty0 = blockIdx.y * 16, tx0 = blockIdx.x * 16;
    int tid = threadIdx.x;
    int lx  = tid & 15, ly = (tid >> 4) & 15, hd = tid >> 8;

    const float* f = feats + (size_t)b * 2 * CC * HW;

    int fgo[NJ], fso[NJ];
    unsigned vm = 0;
    #pragma unroll
    for (int j = 0; j < NJ; j++) {
        int e = tid + j * 512;
        fgo[j] = 0; fso[j] = 0;
        if (e < TEL) {
            int c  = e / 784;
            int rm = e - c * 784;
            int r  = rm / 28;
            int cc = rm - r * 28;
            int gy = ty0 + r - 6, gx = tx0 + cc - 6;
            bool v = ((unsigned)gy < HH) && ((unsigned)gx < WW);
            if (v) vm |= (1u << j);
            fgo[j] = c * HW + (v ? gy : 0) * WW + (v ? gx : 0);
            fso[j] = ((c >> 1) * 28 * 32 + r * 32 + cc) * 2 + (c & 1);
        }
    }
    unsigned su0 = su(&sm2[0][0][0][0]);

    ull acc2[25];
    #pragma unroll
    for (int d = 0; d < 25; d++) acc2[d] = 0ull;

    auto pre = [&](int c0, int s) {
        unsigned base = su0 + (unsigned)(s * BUF) * 4u;
        #pragma unroll
        for (int j = 0; j < NJ; j++) {
            int e = tid + j * 512;
            if (e < TEL)
                cpa4(base + 4u * (unsigned)fso[j], f + (size_t)c0 * HW + fgo[j], (vm >> j) & 1);
        }
    };

    pre(0, 0); CPCOMMIT;
    for (int ch = 0; ch < 32; ch++) {
        int s = ch & 1;
        if (ch < 31) { pre((ch + 1) * 4, s ^ 1); CPCOMMIT; CPWAIT(1); }
        else         { CPWAIT(0); }
        __syncthreads();
        #pragma unroll
        for (int pr = 0; pr < 2; pr++) {
            ull ctr = *(const ull*)&sm2[s][pr][ly + 6][lx + 6];
            if (hd == 0) {
                #pragma unroll
                for (int d = 0; d < 25; d++) {
                    int di = d / 7, dj = d % 7;
                    ull t = *(const ull*)&sm2[s][pr][ly + 2 * di][lx + 2 * dj];
                    fma2(acc2[d], ctr, t);
                }
            } else {
                #pragma unroll
                for (int d = 0; d < 25; d++) {
                    int di = (24 + d) / 7, dj = (24 + d) % 7;
                    ull t = *(const ull*)&sm2[s][pr][ly + 2 * di][lx + 2 * dj];
                    fma2(acc2[d], ctr, t);
                }
            }
        }
        __syncthreads();
    }

    int y = ty0 + ly, x = tx0 + lx;
    float* out = g_xin + (size_t)b * 50 * HW + y * WW + x;
    int D0 = hd * 24;
    #pragma unroll
    for (int d = 0; d < 25; d++) {
        float lo, hi;
        upk(lo, hi, acc2[d]);
        out[(size_t)(D0 + d) * HW] = lrelu(lo + hi) * (1.0f / 128.0f);
    }
}

// ---------------- kernel 3: 3x3 conv, dup-f32x2 smem, 8px x 4oc, 3 blocks/SM -
// 32x32 tile; 256 threads: ty=tid&31 (row), tx=(tid>>5)&3 (8px), og=tid>>7 (2 oc-pairs)
// Block covers 8 output channels.
template<int IC, int OC>
__global__ __launch_bounds__(256, 3) void conv3_kernel(const float* __restrict__ in,
                                                       const float* __restrict__ wt,
                                                       const float* __restrict__ bias,
                                                       float* __restrict__ out)
{
    constexpr int NIC   = 2;
    constexpr int NCH   = IC / NIC;
    constexpr int TELEM = NIC * 34 * 34;          // 2312
    constexpr int NJ    = (TELEM + 255) / 256;    // 10
    __shared__ __align__(16) float2 tin[2][NIC][34][38];
    __shared__ ull wsm[2][4][NIC][9];             // 4 oc-pairs

    int tid = threadIdx.x;
    int ty = tid & 31;
    int tx = (tid >> 5) & 3;
    int og = tid >> 7;
    int bx = blockIdx.x * 32, by = blockIdx.y * 32;
    int bz = blockIdx.z;
    int ocg = bz % (OC / 8);
    int b   = bz / (OC / 8);

    const float* inb = in + (size_t)b * IC * HW;
    const float* wtb = wt + (size_t)(ocg * 8) * IC * 9;

    // ---- precompute packed tile offsets: bit28 valid | [16:28) soff | [0:16) goff
    unsigned pko[NJ];
    #pragma unroll
    for (int j = 0; j < NJ; j++) {
        int e = tid + j * 256;
        pko[j] = 0;
        if (e < TELEM) {
            int cl = e / 1156;
            int rm = e - cl * 1156;
            int r  = rm / 34;
            int cc = rm - r * 34;
            int gy = by + r - 1, gx = bx + cc - 1;
            bool v = ((unsigned)gy < HH) && ((unsigned)gx < WW);
            unsigned go = (unsigned)(cl * HW + (v ? gy : 0) * WW + (v ? gx : 0));
            unsigned so = (unsigned)((cl * 34 + r) * 38 + cc);
            pko[j] = go | (so << 16) | (v ? (1u << 28) : 0u);
        }
    }
    // ---- weight loader offsets (72 active threads) ----
    bool wact = tid < 72;
    int wg0 = 0, wso = 0;
    if (wact) {
        int ocp = tid / 18;              // 0..3
        int rem = tid - ocp * 18;
        int cl = rem / 9, k = rem - cl * 9;
        wg0 = (ocp * 2) * IC * 9 + cl * 9 + k;
        wso = (ocp * NIC + cl) * 9 + k;
    }

    ull acc[2][8];
    #pragma unroll
    for (int o = 0; o < 2; o++)
        #pragma unroll
        for (int p = 0; p < 8; p++) acc[o][p] = 0ull;

    float tv[NJ];
    float wa, wb;

    auto ldt = [&](int ic0) {
        const float* src = inb + (size_t)ic0 * HW;
        #pragma unroll
        for (int j = 0; j < NJ; j++) {
            int e = tid + j * 256;
            if (e < TELEM)
                tv[j] = (pko[j] >> 28) ? __ldg(src + (pko[j] & 0xFFFFu)) : 0.f;
        }
    };
    auto stt = [&](int s) {
        float2* tf = &tin[s][0][0][0];
        #pragma unroll
        for (int j = 0; j < NJ; j++) {
            int e = tid + j * 256;
            if (e < TELEM) tf[(pko[j] >> 16) & 0xFFFu] = make_float2(tv[j], tv[j]);
        }
    };
    auto ldw = [&](int ic0) {
        if (wact) {
            const float* p = wtb + wg0 + ic0 * 9;
            wa = p[0]; wb = p[IC * 9];
        }
    };
    auto stw = [&](int s) {
        if (wact) ((ull*)wsm)[s * 72 + wso] = pk(wa, wb);
    };

    ldt(0); ldw(0);
    stt(0); stw(0);

    for (int ch = 0; ch < NCH; ch++) {
        int s = ch & 1;
        if (ch + 1 < NCH) { ldt((ch + 1) * NIC); ldw((ch + 1) * NIC); }
        __syncthreads();

        #pragma unroll
        for (int cl = 0; cl < NIC; cl++) {
            #pragma unroll
            for (int ky = 0; ky < 3; ky++) {
                const ulonglong2* rp = (const ulonglong2*)&tin[s][cl][ty + ky][8 * tx];
                ull vv[10];
                #pragma unroll
                for (int i = 0; i < 5; i++) {
                    ulonglong2 t = rp[i];
                    vv[2 * i] = t.x; vv[2 * i + 1] = t.y;
                }
                #pragma unroll
                for (int o2 = 0; o2 < 2; o2++) {
                    const ull* wp = &wsm[s][og * 2 + o2][cl][ky * 3];
                    ull w0 = wp[0], w1 = wp[1], w2 = wp[2];
                    #pragma unroll
                    for (int p = 0; p < 8; p++) {
                        fma2(acc[o2][p], vv[p],     w0);
                        fma2(acc[o2][p], vv[p + 1], w1);
                        fma2(acc[o2][p], vv[p + 2], w2);
                    }
                }
            }
        }
        if (ch + 1 < NCH) { stt(s ^ 1); stw(s ^ 1); }
    }

    int y = by + ty, xb = bx + 8 * tx;
    #pragma unroll
    for (int o2 = 0; o2 < 2; o2++) {
        int oc0 = ocg * 8 + (og * 2 + o2) * 2;
        float b0 = bias[oc0], b1 = bias[oc0 + 1];
        float r0[8], r1[8];
        #pragma unroll
        for (int p = 0; p < 8; p++) {
            float lo, hi;
            upk(lo, hi, acc[o2][p]);
            r0[p] = lrelu(lo + b0);
            r1[p] = lrelu(hi + b1);
        }
        float* op0 = out + ((size_t)(b * OC + oc0) * HH + y) * WW + xb;
        float* op1 = op0 + HW;
        *(float4*)(op0)     = make_float4(r0[0], r0[1], r0[2], r0[3]);
        *(float4*)(op0 + 4) = make_float4(r0[4], r0[5], r0[6], r0[7]);
        *(float4*)(op1)     = make_float4(r1[0], r1[1], r1[2], r1[3]);
        *(float4*)(op1 + 4) = make_float4(r1[4], r1[5], r1[6], r1[7]);
    }
}

// ---------------- kernel 4: 5x5 heads + warp + sigmoid -----------------------
__global__ __launch_bounds__(256) void head_kernel(const float* __restrict__ disp_w,
                                                   const float* __restrict__ disp_b,
                                                   const float* __restrict__ conf_w,
                                                   const float* __restrict__ conf_b,
                                                   float* __restrict__ out)
{
    __shared__ float sm[8][20][20];
    __shared__ float wsm[3][32][25];
    int tid = threadIdx.x;
    int lx = tid & 15, ly = tid >> 4;
    int b = blockIdx.z;
    int ty0 = blockIdx.y * 16, tx0 = blockIdx.x * 16;

    for (int e = tid; e < 3 * 32 * 25; e += 256) {
        int o = e / (32 * 25);
        int rem = e % (32 * 25);
        float v = (o < 2) ? disp_w[o * 32 * 25 + rem] : conf_w[rem];
        wsm[o][rem / 25][rem % 25] = v;
    }

    const float* x3 = g_x3 + (size_t)b * 32 * HW;
    float d0 = 0.f, d1 = 0.f, cf = 0.f;

    for (int c0 = 0; c0 < 32; c0 += 8) {
        __syncthreads();
        for (int e = tid; e < 8 * 400; e += 256) {
            int cl = e / 400;
            int r  = (e % 400) / 20;
            int cc = e % 20;
            int gy = ty0 + r - 2, gx = tx0 + cc - 2;
            float v = 0.f;
            if ((unsigned)gy < HH && (unsigned)gx < WW)
                v = x3[(size_t)(c0 + cl) * HW + gy * WW + gx];
            sm[cl][r][cc] = v;
        }
        __syncthreads();
        #pragma unroll
        for (int cl = 0; cl < 8; cl++) {
            int ic = c0 + cl;
            #pragma unroll
            for (int ky = 0; ky < 5; ky++) {
                #pragma unroll
                for (int kx = 0; kx < 5; kx++) {
                    float v = sm[cl][ly + ky][lx + kx];
                    int k = ky * 5 + kx;
                    d0 += v * wsm[0][ic][k];
                    d1 += v * wsm[1][ic][k];
                    cf += v * wsm[2][ic][k];
                }
            }
        }
    }
    d0 += disp_b[0];
    d1 += disp_b[1];
    cf += conf_b[0];

    int y = ty0 + ly, x = tx0 + lx;

    const float* uf = g_upflow + (size_t)b * 2 * HW;
    float px = (float)x + d0;
    float py = (float)y + d1;
    float x0f = floorf(px), y0f = floorf(py);
    float wx1 = px - x0f, wx0 = 1.0f - wx1;
    float wy1 = py - y0f, wy0 = 1.0f - wy1;

    float vc0[4], vc1[4], mm[4];
    float xs[4] = {x0f, x0f + 1.0f, x0f, x0f + 1.0f};
    float ys[4] = {y0f, y0f, y0f + 1.0f, y0f + 1.0f};
    #pragma unroll
    for (int q = 0; q < 4; q++) {
        float xi = xs[q], yi = ys[q];
        bool valid = (xi >= 0.f) && (xi <= (float)(WW - 1)) &&
                     (yi >= 0.f) && (yi <= (float)(HH - 1));
        float xc = fminf(fmaxf(xi, 0.f), (float)(WW - 1));
        float yc = fminf(fmaxf(yi, 0.f), (float)(HH - 1));
        int idx = (int)yc * WW + (int)xc;
        mm[q]  = valid ? 1.f : 0.f;
        vc0[q] = valid ? uf[idx] : 0.f;
        vc1[q] = valid ? uf[HW + idx] : 0.f;
    }
    float out0 = wy0 * (wx0 * vc0[0] + wx1 * vc0[1]) + wy1 * (wx0 * vc0[2] + wx1 * vc0[3]);
    float out1 = wy0 * (wx0 * vc1[0] + wx1 * vc1[1]) + wy1 * (wx0 * vc1[2] + wx1 * vc1[3]);
    float msk  = wy0 * (wx0 * mm[0] + wx1 * mm[1]) + wy1 * (wx0 * mm[2] + wx1 * mm[3]);
    float mask = (msk >= 1.0f) ? 1.f : 0.f;

    out[((size_t)(b * 2 + 0) * HH + y) * WW + x] = out0 * mask;
    out[((size_t)(b * 2 + 1) * HH + y) * WW + x] = out1 * mask;
    out[(size_t)BB * 2 * HW + ((size_t)b * HH + y) * WW + x] = 1.0f / (1.0f + expf(-cf));
}

// ---------------- launch -----------------------------------------------------
extern "C" void kernel_launch(void* const* d_in, const int* in_sizes, int n_in,
                              void* d_out, int out_size)
{
    const float* feats     = (const float*)d_in[0];
    const float* flow      = (const float*)d_in[1];
    const float* conf      = (const float*)d_in[2];
    const float* up_conf_w = (const float*)d_in[3];
    const float* up_flow_w = (const float*)d_in[4];
    const float* w1        = (const float*)d_in[5];
    const float* b1        = (const float*)d_in[6];
    const float* w2        = (const float*)d_in[7];
    const float* b2        = (const float*)d_in[8];
    const float* w3        = (const float*)d_in[9];
    const float* b3        = (const float*)d_in[10];
    const float* disp_w    = (const float*)d_in[11];
    const float* disp_b    = (const float*)d_in[12];
    const float* conf_w    = (const float*)d_in[13];
    const float* conf_b    = (const float*)d_in[14];
    float* out = (float*)d_out;

    float *xin, *x1, *x2, *x3;
    cudaGetSymbolAddress((void**)&xin, g_xin);
    cudaGetSymbolAddress((void**)&x1,  g_x1);
    cudaGetSymbolAddress((void**)&x2,  g_x2);
    cudaGetSymbolAddress((void**)&x3,  g_x3);

    deconv_kernel<<<(BB * 3 * HW + 255) / 256, 256>>>(flow, conf, up_flow_w, up_conf_w);
    corr_kernel<<<dim3(10, 10, BB), 512>>>(feats);
    conv3_kernel<50, 128><<<dim3(5, 5, BB * 16), 256>>>(xin, w1, b1, x1);
    conv3_kernel<128, 64><<<dim3(5, 5, BB * 8),  256>>>(x1, w2, b2, x2);
    conv3_kernel<64, 32><<<dim3(5, 5, BB * 4),  256>>>(x2, w3, b3, x3);
    head_kernel<<<dim3(10, 10, BB), 256>>>(disp_w, disp_b, conf_w, conf_b, out);
}

// round 12
// speedup vs baseline: 1.2303x; 1.2303x over previous
#include <cuda_runtime.h>
#include <math.h>

#define BB 8
#define CC 128
#define HH 160
#define WW 160
#define HW (HH*WW)
#define Hh 80
#define Wh 80

typedef unsigned long long ull;

// ---------------- scratch ----------------------------------------------------
__device__ float g_upflow[BB*2*HW];
__device__ float g_xin[BB*50*HW];
__device__ float g_x1[BB*128*HW];
__device__ float g_x2[BB*64*HW];
__device__ float g_x3[BB*32*HW];

__device__ __forceinline__ float lrelu(float v) { return v > 0.f ? v : 0.1f * v; }

__device__ __forceinline__ void fma2(ull &d, ull a, ull b) {
    asm("fma.rn.f32x2 %0, %1, %2, %0;" : "+l"(d) : "l"(a), "l"(b));
}
__device__ __forceinline__ ull pk(float lo, float hi) {
    ull r;
    asm("mov.b64 %0, {%1, %2};" : "=l"(r) : "f"(lo), "f"(hi));
    return r;
}
__device__ __forceinline__ void upk(float &lo, float &hi, ull p) {
    asm("mov.b64 {%0, %1}, %2;" : "=f"(lo), "=f"(hi) : "l"(p));
}

__device__ __forceinline__ unsigned su(const void* p) {
    return (unsigned)__cvta_generic_to_shared(p);
}
__device__ __forceinline__ void cpa4(unsigned dst, const float* src, bool v) {
    int sz = v ? 4 : 0;
    asm volatile("cp.async.ca.shared.global [%0], [%1], 4, %2;" :: "r"(dst), "l"(src), "r"(sz));
}
#define CPCOMMIT asm volatile("cp.async.commit_group;")
#define CPWAIT(N) asm volatile("cp.async.wait_group %0;" :: "n"(N))

// ---------------- kernel 1: transposed-conv upsampling -----------------------
__global__ void deconv_kernel(const float* __restrict__ flow,
                              const float* __restrict__ conf,
                              const float* __restrict__ wf,
                              const float* __restrict__ wc)
{
    int i = blockIdx.x * blockDim.x + threadIdx.x;
    if (i >= BB * 3 * HW) return;
    int x  = i % WW;
    int y  = (i / WW) % HH;
    int ch = (i / HW) % 3;
    int b  = i / (3 * HW);

    const float* w;
    const float* in;
    if (ch < 2) { w = wf + ch * 16; in = flow + (b * 2 + ch) * (Hh * Wh); }
    else        { w = wc;           in = conf + b * (Hh * Wh); }

    float acc = 0.f;
    #pragma unroll
    for (int ky = 0; ky < 4; ky++) {
        int t = y + 1 - ky;
        if (t & 1) continue;
        int iy = t >> 1;
        if ((unsigned)iy >= Hh) continue;
        #pragma unroll
        for (int kx = 0; kx < 4; kx++) {
            int u = x + 1 - kx;
            if (u & 1) continue;
            int ix = u >> 1;
            if ((unsigned)ix >= Wh) continue;
            acc += in[iy * Wh + ix] * w[ky * 4 + kx];
        }
    }
    if (ch < 2) g_upflow[(b * 2 + ch) * HW + y * WW + x] = acc;
    else        g_xin[((size_t)b * 50 + 49) * HW + y * WW + x] = acc;
}

// ---------------- kernel 2: 7x7 dilated self-correlation ---------------------
__global__ __launch_bounds__(512) void corr_kernel(const float* __restrict__ feats)
{
    __shared__ float2 sm2[2][2][28][32];
    constexpr int TEL = 4 * 28 * 28;            // 3136
    constexpr int NJ  = (TEL + 511) / 512;      // 7
    constexpr int BUF = 2 * 28 * 32 * 2;        // floats per buffer

    int b   = blockIdx.z;
    int ty0 = blockIdx.y * 16, tx0 = blockIdx.x * 16;
    int tid = threadIdx.x;
    int lx  = tid & 15, ly = (tid >> 4) & 15, hd = tid >> 8;

    const float* f = feats + (size_t)b * 2 * CC * HW;

    int fgo[NJ], fso[NJ];
    unsigned vm = 0;
    #pragma unroll
    for (int j = 0; j < NJ; j++) {
        int e = tid + j * 512;
        fgo[j] = 0; fso[j] = 0;
        if (e < TEL) {
            int c  = e / 784;
            int rm = e - c * 784;
            int r  = rm / 28;
            int cc = rm - r * 28;
            int gy = ty0 + r - 6, gx = tx0 + cc - 6;
            bool v = ((unsigned)gy < HH) && ((unsigned)gx < WW);
            if (v) vm |= (1u << j);
            fgo[j] = c * HW + (v ? gy : 0) * WW + (v ? gx : 0);
            fso[j] = ((c >> 1) * 28 * 32 + r * 32 + cc) * 2 + (c & 1);
        }
    }
    unsigned su0 = su(&sm2[0][0][0][0]);

    ull acc2[25];
    #pragma unroll
    for (int d = 0; d < 25; d++) acc2[d] = 0ull;

    auto pre = [&](int c0, int s) {
        unsigned base = su0 + (unsigned)(s * BUF) * 4u;
        #pragma unroll
        for (int j = 0; j < NJ; j++) {
            int e = tid + j * 512;
            if (e < TEL)
                cpa4(base + 4u * (unsigned)fso[j], f + (size_t)c0 * HW + fgo[j], (vm >> j) & 1);
        }
    };

    pre(0, 0); CPCOMMIT;
    for (int ch = 0; ch < 32; ch++) {
        int s = ch & 1;
        if (ch < 31) { pre((ch + 1) * 4, s ^ 1); CPCOMMIT; CPWAIT(1); }
        else         { CPWAIT(0); }
        __syncthreads();
        #pragma unroll
        for (int pr = 0; pr < 2; pr++) {
            ull ctr = *(const ull*)&sm2[s][pr][ly + 6][lx + 6];
            if (hd == 0) {
                #pragma unroll
                for (int d = 0; d < 25; d++) {
                    int di = d / 7, dj = d % 7;
                    ull t = *(const ull*)&sm2[s][pr][ly + 2 * di][lx + 2 * dj];
                    fma2(acc2[d], ctr, t);
                }
            } else {
                #pragma unroll
                for (int d = 0; d < 25; d++) {
                    int di = (24 + d) / 7, dj = (24 + d) % 7;
                    ull t = *(const ull*)&sm2[s][pr][ly + 2 * di][lx + 2 * dj];
                    fma2(acc2[d], ctr, t);
                }
            }
        }
        __syncthreads();
    }

    int y = ty0 + ly, x = tx0 + lx;
    float* out = g_xin + (size_t)b * 50 * HW + y * WW + x;
    int D0 = hd * 24;
    #pragma unroll
    for (int d = 0; d < 25; d++) {
        float lo, hi;
        upk(lo, hi, acc2[d]);
        out[(size_t)(D0 + d) * HW] = lrelu(lo + hi) * (1.0f / 128.0f);
    }
}

// ---------------- kernel 3: 3x3 conv, plain-float tile via cp.async, --------
// MOV-packed f32x2 operands. 32x32 tile; 256 threads:
// ty=tid&31 (row), tx=(tid>>5)&3 (8px), og=tid>>7 (2 oc-pairs). Block = 8 oc.
template<int IC, int OC>
__global__ __launch_bounds__(256, 3) void conv3_kernel(const float* __restrict__ in,
                                                       const float* __restrict__ wt,
                                                       const float* __restrict__ bias,
                                                       float* __restrict__ out)
{
    constexpr int NIC   = 2;
    constexpr int NCH   = IC / NIC;
    constexpr int TELEM = NIC * 34 * 34;          // 2312
    constexpr int NJ    = (TELEM + 255) / 256;    // 10
    constexpr int TBUF  = NIC * 34 * 36;          // floats per buffer (2448)
    __shared__ __align__(16) float tin[2][NIC][34][36];
    __shared__ ull wsm[2][4][NIC][9];             // 4 oc-pairs

    int tid = threadIdx.x;
    int ty = tid & 31;
    int tx = (tid >> 5) & 3;
    int og = tid >> 7;
    int bx = blockIdx.x * 32, by = blockIdx.y * 32;
    int bz = blockIdx.z;
    int ocg = bz % (OC / 8);
    int b   = bz / (OC / 8);

    const float* inb = in + (size_t)b * IC * HW;
    const float* wtb = wt + (size_t)(ocg * 8) * IC * 9;

    // ---- packed tile offsets: bit28 valid | [16:28) soff | [0:16) goff ----
    // goff max = HW + 25599 = 51199 < 2^16; soff max = (67*36+35) = 2447 < 2^12
    unsigned pko[NJ];
    #pragma unroll
    for (int j = 0; j < NJ; j++) {
        int e = tid + j * 256;
        pko[j] = 0;
        if (e < TELEM) {
            int cl = e / 1156;
            int rm = e - cl * 1156;
            int r  = rm / 34;
            int cc = rm - r * 34;
            int gy = by + r - 1, gx = bx + cc - 1;
            bool v = ((unsigned)gy < HH) && ((unsigned)gx < WW);
            unsigned go = (unsigned)(cl * HW + (v ? gy : 0) * WW + (v ? gx : 0));
            unsigned so = (unsigned)((cl * 34 + r) * 36 + cc);
            pko[j] = go | (so << 16) | (v ? (1u << 28) : 0u);
        }
    }
    // ---- weight loader offsets (72 active threads) ----
    bool wact = tid < 72;
    int wg0 = 0, wso = 0;
    if (wact) {
        int ocp = tid / 18;              // 0..3
        int rem = tid - ocp * 18;
        int cl = rem / 9, k = rem - cl * 9;
        wg0 = (ocp * 2) * IC * 9 + cl * 9 + k;
        wso = (ocp * NIC + cl) * 9 + k;
    }

    ull acc[2][8];
    #pragma unroll
    for (int o = 0; o < 2; o++)
        #pragma unroll
        for (int p = 0; p < 8; p++) acc[o][p] = 0ull;

    float wa, wb;
    unsigned tb0 = su(&tin[0][0][0][0]);

    auto pre = [&](int ic0, int s) {
        const float* src = inb + (size_t)ic0 * HW;
        unsigned base = tb0 + (unsigned)(s * TBUF) * 4u;
        #pragma unroll
        for (int j = 0; j < NJ; j++) {
            int e = tid + j * 256;
            if (e < TELEM)
                cpa4(base + 4u * ((pko[j] >> 16) & 0xFFFu),
                     src + (pko[j] & 0xFFFFu), (pko[j] >> 28) & 1);
        }
    };
    auto ldw = [&](int ic0) {
        if (wact) {
            const float* p = wtb + wg0 + ic0 * 9;
            wa = p[0]; wb = p[IC * 9];
        }
    };
    auto stw = [&](int s) {
        if (wact) ((ull*)wsm)[s * 72 + wso] = pk(wa, wb);
    };

    pre(0, 0); CPCOMMIT;
    ldw(0); stw(0);

    for (int ch = 0; ch < NCH; ch++) {
        int s = ch & 1;
        if (ch + 1 < NCH) {
            pre((ch + 1) * NIC, s ^ 1); CPCOMMIT;
            ldw((ch + 1) * NIC);
            CPWAIT(1);
        } else {
            CPWAIT(0);
        }
        __syncthreads();

        #pragma unroll
        for (int cl = 0; cl < NIC; cl++) {
            #pragma unroll
            for (int ky = 0; ky < 3; ky++) {
                const float* row = &tin[s][cl][ty + ky][8 * tx];
                float4 a0 = *(const float4*)row;        // px 0..3
                float4 a1 = *(const float4*)(row + 4);  // px 4..7
                float2 ee = *(const float2*)(row + 8);  // px 8..9 (halo)
                ull vv[10];
                vv[0] = pk(a0.x, a0.x); vv[1] = pk(a0.y, a0.y);
                vv[2] = pk(a0.z, a0.z); vv[3] = pk(a0.w, a0.w);
                vv[4] = pk(a1.x, a1.x); vv[5] = pk(a1.y, a1.y);
                vv[6] = pk(a1.z, a1.z); vv[7] = pk(a1.w, a1.w);
                vv[8] = pk(ee.x, ee.x); vv[9] = pk(ee.y, ee.y);
                #pragma unroll
                for (int o2 = 0; o2 < 2; o2++) {
                    const ull* wp = &wsm[s][og * 2 + o2][cl][ky * 3];
                    ull w0 = wp[0], w1 = wp[1], w2 = wp[2];
                    #pragma unroll
                    for (int p = 0; p < 8; p++) {
                        fma2(acc[o2][p], vv[p],     w0);
                        fma2(acc[o2][p], vv[p + 1], w1);
                        fma2(acc[o2][p], vv[p + 2], w2);
                    }
                }
            }
        }
        if (ch + 1 < NCH) stw(s ^ 1);
        __syncthreads();
    }

    int y = by + ty, xb = bx + 8 * tx;
    #pragma unroll
    for (int o2 = 0; o2 < 2; o2++) {
        int oc0 = ocg * 8 + (og * 2 + o2) * 2;
        float b0 = bias[oc0], b1 = bias[oc0 + 1];
        float r0[8], r1[8];
        #pragma unroll
        for (int p = 0; p < 8; p++) {
            float lo, hi;
            upk(lo, hi, acc[o2][p]);
            r0[p] = lrelu(lo + b0);
            r1[p] = lrelu(hi + b1);
        }
        float* op0 = out + ((size_t)(b * OC + oc0) * HH + y) * WW + xb;
        float* op1 = op0 + HW;
        *(float4*)(op0)     = make_float4(r0[0], r0[1], r0[2], r0[3]);
        *(float4*)(op0 + 4) = make_float4(r0[4], r0[5], r0[6], r0[7]);
        *(float4*)(op1)     = make_float4(r1[0], r1[1], r1[2], r1[3]);
        *(float4*)(op1 + 4) = make_float4(r1[4], r1[5], r1[6], r1[7]);
    }
}

// ---------------- kernel 4: 5x5 heads + warp + sigmoid -----------------------
__global__ __launch_bounds__(256) void head_kernel(const float* __restrict__ disp_w,
                                                   const float* __restrict__ disp_b,
                                                   const float* __restrict__ conf_w,
                                                   const float* __restrict__ conf_b,
                                                   float* __restrict__ out)
{
    __shared__ float sm[8][20][20];
    __shared__ float wsm[3][32][25];
    int tid = threadIdx.x;
    int lx = tid & 15, ly = tid >> 4;
    int b = blockIdx.z;
    int ty0 = blockIdx.y * 16, tx0 = blockIdx.x * 16;

    for (int e = tid; e < 3 * 32 * 25; e += 256) {
        int o = e / (32 * 25);
        int rem = e % (32 * 25);
        float v = (o < 2) ? disp_w[o * 32 * 25 + rem] : conf_w[rem];
        wsm[o][rem / 25][rem % 25] = v;
    }

    const float* x3 = g_x3 + (size_t)b * 32 * HW;
    float d0 = 0.f, d1 = 0.f, cf = 0.f;

    for (int c0 = 0; c0 < 32; c0 += 8) {
        __syncthreads();
        for (int e = tid; e < 8 * 400; e += 256) {
            int cl = e / 400;
            int r  = (e % 400) / 20;
            int cc = e % 20;
            int gy = ty0 + r - 2, gx = tx0 + cc - 2;
            float v = 0.f;
            if ((unsigned)gy < HH && (unsigned)gx < WW)
                v = x3[(size_t)(c0 + cl) * HW + gy * WW + gx];
            sm[cl][r][cc] = v;
        }
        __syncthreads();
        #pragma unroll
        for (int cl = 0; cl < 8; cl++) {
            int ic = c0 + cl;
            #pragma unroll
            for (int ky = 0; ky < 5; ky++) {
                #pragma unroll
                for (int kx = 0; kx < 5; kx++) {
                    float v = sm[cl][ly + ky][lx + kx];
                    int k = ky * 5 + kx;
                    d0 += v * wsm[0][ic][k];
                    d1 += v * wsm[1][ic][k];
                    cf += v * wsm[2][ic][k];
                }
            }
        }
    }
    d0 += disp_b[0];
    d1 += disp_b[1];
    cf += conf_b[0];

    int y = ty0 + ly, x = tx0 + lx;

    const float* uf = g_upflow + (size_t)b * 2 * HW;
    float px = (float)x + d0;
    float py = (float)y + d1;
    float x0f = floorf(px), y0f = floorf(py);
    float wx1 = px - x0f, wx0 = 1.0f - wx1;
    float wy1 = py - y0f, wy0 = 1.0f - wy1;

    float vc0[4], vc1[4], mm[4];
    float xs[4] = {x0f, x0f + 1.0f, x0f, x0f + 1.0f};
    float ys[4] = {y0f, y0f, y0f + 1.0f, y0f + 1.0f};
    #pragma unroll
    for (int q = 0; q < 4; q++) {
        float xi = xs[q], yi = ys[q];
        bool valid = (xi >= 0.f) && (xi <= (float)(WW - 1)) &&
                     (yi >= 0.f) && (yi <= (float)(HH - 1));
        float xc = fminf(fmaxf(xi, 0.f), (float)(WW - 1));
        float yc = fminf(fmaxf(yi, 0.f), (float)(HH - 1));
        int idx = (int)yc * WW + (int)xc;
        mm[q]  = valid ? 1.f : 0.f;
        vc0[q] = valid ? uf[idx] : 0.f;
        vc1[q] = valid ? uf[HW + idx] : 0.f;
    }
    float out0 = wy0 * (wx0 * vc0[0] + wx1 * vc0[1]) + wy1 * (wx0 * vc0[2] + wx1 * vc0[3]);
    float out1 = wy0 * (wx0 * vc1[0] + wx1 * vc1[1]) + wy1 * (wx0 * vc1[2] + wx1 * vc1[3]);
    float msk  = wy0 * (wx0 * mm[0] + wx1 * mm[1]) + wy1 * (wx0 * mm[2] + wx1 * mm[3]);
    float mask = (msk >= 1.0f) ? 1.f : 0.f;

    out[((size_t)(b * 2 + 0) * HH + y) * WW + x] = out0 * mask;
    out[((size_t)(b * 2 + 1) * HH + y) * WW + x] = out1 * mask;
    out[(size_t)BB * 2 * HW + ((size_t)b * HH + y) * WW + x] = 1.0f / (1.0f + expf(-cf));
}

// ---------------- launch -----------------------------------------------------
extern "C" void kernel_launch(void* const* d_in, const int* in_sizes, int n_in,
                              void* d_out, int out_size)
{
    const float* feats     = (const float*)d_in[0];
    const float* flow      = (const float*)d_in[1];
    const float* conf      = (const float*)d_in[2];
    const float* up_conf_w = (const float*)d_in[3];
    const float* up_flow_w = (const float*)d_in[4];
    const float* w1        = (const float*)d_in[5];
    const float* b1        = (const float*)d_in[6];
    const float* w2        = (const float*)d_in[7];
    const float* b2        = (const float*)d_in[8];
    const float* w3        = (const float*)d_in[9];
    const float* b3        = (const float*)d_in[10];
    const float* disp_w    = (const float*)d_in[11];
    const float* disp_b    = (const float*)d_in[12];
    const float* conf_w    = (const float*)d_in[13];
    const float* conf_b    = (const float*)d_in[14];
    float* out = (float*)d_out;

    float *xin, *x1, *x2, *x3;
    cudaGetSymbolAddress((void**)&xin, g_xin);
    cudaGetSymbolAddress((void**)&x1,  g_x1);
    cudaGetSymbolAddress((void**)&x2,  g_x2);
    cudaGetSymbolAddress((void**)&x3,  g_x3);

    deconv_kernel<<<(BB * 3 * HW + 255) / 256, 256>>>(flow, conf, up_flow_w, up_conf_w);
    corr_kernel<<<dim3(10, 10, BB), 512>>>(feats);
    conv3_kernel<50, 128><<<dim3(5, 5, BB * 16), 256>>>(xin, w1, b1, x1);
    conv3_kernel<128, 64><<<dim3(5, 5, BB * 8),  256>>>(x1, w2, b2, x2);
    conv3_kernel<64, 32><<<dim3(5, 5, BB * 4),  256>>>(x2, w3, b3, x3);
    head_kernel<<<dim3(10, 10, BB), 256>>>(disp_w, disp_b, conf_w, conf_b, out);
}